// round 4
// baseline (speedup 1.0000x reference)
#include <cuda_runtime.h>
#include <cuda_bf16.h>
#include <cstdint>

#define N_NODES 50000
#define N_EDGES 640000
#define NPAD    50048      // 391 * 128, padded row count for GEMM A-tiles

// ---------------- device scratch (allocation-free rule: __device__ globals) ---
__device__ alignas(16)  int   g_is64;
__device__ alignas(16)  int   g_src[N_EDGES];
__device__ alignas(16)  int   g_dst[N_EDGES];
__device__ alignas(16)  int   g_cnt[N_NODES];
__device__ alignas(16)  int   g_rowptr[N_NODES + 1];
__device__ alignas(16)  int   g_fill[N_NODES];
__device__ alignas(16)  int   g_perm[N_EDGES];
__device__ alignas(256) float g_xp[(size_t)NPAD * 128];     // padded copy of x
__device__ alignas(256) float g_mean1[(size_t)NPAD * 128];
__device__ alignas(256) float g_h[(size_t)NPAD * 256];
__device__ alignas(256) float g_mean2[(size_t)NPAD * 256];

// ---------------- edge dtype detection + conversion ---------------------------
// JAX without x64 silently downcasts int64->int32, so edge_index may be either
// int32 [2,E] or int64 [2,E]. Little-endian int64 values < 2^31 look like
// (val, 0) int32 pairs; node ids are < 50000, so checking 64 odd slots for
// zero identifies int64 with overwhelming certainty.
__global__ void k_detect(const int* __restrict__ ei32) {
    int is64 = 1;
    for (int i = 0; i < 64; i++)
        if (ei32[2 * i + 1] != 0) { is64 = 0; break; }
    g_is64 = is64;
}

__global__ void k_conv(const int* __restrict__ ei32) {
    int i = blockIdx.x * blockDim.x + threadIdx.x;
    if (i >= N_EDGES) return;
    int s, d;
    if (g_is64) {
        s = ei32[2 * i];                    // low word of src[i]
        d = ei32[2 * (N_EDGES + i)];        // low word of dst[i]
    } else {
        s = ei32[i];
        d = ei32[N_EDGES + i];
    }
    // clamp defensively so a wrong guess can never fault (result would just
    // be wrong and caught by the checker, not crash)
    g_src[i] = min(max(s, 0), N_NODES - 1);
    g_dst[i] = min(max(d, 0), N_NODES - 1);
}

// ---------------- CSR construction --------------------------------------------
__global__ void k_zero_cnt() {
    int i = blockIdx.x * blockDim.x + threadIdx.x;
    if (i < N_NODES) g_cnt[i] = 0;
}

__global__ void k_hist() {
    int i = blockIdx.x * blockDim.x + threadIdx.x;
    if (i < N_EDGES) atomicAdd(&g_cnt[g_dst[i]], 1);
}

// single-block exclusive scan over 50000 counts (1024 threads, chunked)
__global__ void k_scan() {
    __shared__ int s[1024];
    const int t = threadIdx.x;
    const int chunk = (N_NODES + 1023) / 1024;   // 49
    const int beg = t * chunk;
    const int end = min(beg + chunk, N_NODES);
    int sum = 0;
    for (int i = beg; i < end; i++) sum += g_cnt[i];
    s[t] = sum;
    __syncthreads();
    for (int off = 1; off < 1024; off <<= 1) {
        int v = 0;
        if (t >= off) v = s[t - off];
        __syncthreads();
        if (t >= off) s[t] += v;
        __syncthreads();
    }
    int run = (t == 0) ? 0 : s[t - 1];
    for (int i = beg; i < end; i++) {
        g_rowptr[i] = run;
        g_fill[i]   = run;
        run += g_cnt[i];
    }
    if (t == 0) g_rowptr[N_NODES] = N_EDGES;
}

__global__ void k_scatter() {
    int i = blockIdx.x * blockDim.x + threadIdx.x;
    if (i < N_EDGES) {
        int pos = atomicAdd(&g_fill[g_dst[i]], 1);
        g_perm[pos] = g_src[i];
    }
}

// padded copy of x so GEMM A-loads never go out of bounds
__global__ void k_copy_x(const float* __restrict__ x) {
    int i = blockIdx.x * blockDim.x + threadIdx.x;
    const int n4 = N_NODES * 128 / 4;
    if (i < n4) {
        ((float4*)g_xp)[i] = ((const float4*)x)[i];
    }
}

// ---------------- mean aggregation: one warp per node -------------------------
template <int CH>
__device__ __forceinline__ void agg_impl(const float* __restrict__ feat,
                                         float* __restrict__ out) {
    const int gwarp = (blockIdx.x * blockDim.x + threadIdx.x) >> 5;
    const int lane  = threadIdx.x & 31;
    if (gwarp >= N_NODES) return;
    const int beg = g_rowptr[gwarp];
    const int end = g_rowptr[gwarp + 1];
    constexpr int F4 = CH / 128;   // float4 chunks per lane (1 or 2)
    float4 acc[F4];
#pragma unroll
    for (int f = 0; f < F4; f++) acc[f] = make_float4(0.f, 0.f, 0.f, 0.f);
    for (int e = beg; e < end; e++) {
        const int s = g_perm[e];
        const float4* p = (const float4*)(feat + (size_t)s * CH);
#pragma unroll
        for (int f = 0; f < F4; f++) {
            float4 v = p[lane + f * 32];
            acc[f].x += v.x; acc[f].y += v.y; acc[f].z += v.z; acc[f].w += v.w;
        }
    }
    const float inv = 1.0f / (float)max(end - beg, 1);
    float4* o = (float4*)(out + (size_t)gwarp * CH);
#pragma unroll
    for (int f = 0; f < F4; f++) {
        float4 v = acc[f];
        v.x *= inv; v.y *= inv; v.z *= inv; v.w *= inv;
        o[lane + f * 32] = v;
    }
}

__global__ void k_agg1() { agg_impl<128>(g_xp, g_mean1); }
__global__ void k_agg2() { agg_impl<256>(g_h,  g_mean2); }

// ---------------- fused dual-GEMM: C = A1@B1 + A2@B2 + bias (+ReLU) -----------
template <bool RELU>
__device__ __forceinline__ void
gemm_impl(const float* __restrict__ A1, int K1, const float* __restrict__ B1,
          const float* __restrict__ A2, int K2, const float* __restrict__ B2,
          const float* __restrict__ bias,
          float* __restrict__ C, int ldc, int Ncols, int Mstore) {
    constexpr int BM = 128, BN = 128, BK = 16;
    __shared__ float As[BK][BM];
    __shared__ float Bs[BK][BN];
    const int tid = threadIdx.x;
    const int tx = tid % 16;
    const int ty = tid / 16;
    const int brow = blockIdx.y * BM;
    const int bcol = blockIdx.x * BN;

    float acc[8][8];
#pragma unroll
    for (int i = 0; i < 8; i++)
#pragma unroll
        for (int j = 0; j < 8; j++) acc[i][j] = 0.f;

#pragma unroll 1
    for (int pass = 0; pass < 2; pass++) {
        const float* A = pass ? A2 : A1;
        const float* B = pass ? B2 : B1;
        const int K = pass ? K2 : K1;
        const int lda = K;
        const int ldb = Ncols;
#pragma unroll 1
        for (int k0 = 0; k0 < K; k0 += BK) {
            {
                const int r = tid / 4;            // 0..63
                const int c = (tid % 4) * 4;      // 0,4,8,12
#pragma unroll
                for (int rr = 0; rr < 2; rr++) {
                    const int row = r + rr * 64;
                    float4 v = *(const float4*)&A[(size_t)(brow + row) * lda + k0 + c];
                    As[c + 0][row] = v.x;
                    As[c + 1][row] = v.y;
                    As[c + 2][row] = v.z;
                    As[c + 3][row] = v.w;
                }
            }
            {
                const int r = tid / 32;           // 0..7
                const int c = (tid % 32) * 4;
#pragma unroll
                for (int rr = 0; rr < 2; rr++) {
                    const int row = r + rr * 8;
                    float4 v = *(const float4*)&B[(size_t)(k0 + row) * ldb + bcol + c];
                    *(float4*)&Bs[row][c] = v;
                }
            }
            __syncthreads();
#pragma unroll
            for (int k = 0; k < BK; k++) {
                float a[8], b[8];
                *(float4*)&a[0] = *(const float4*)&As[k][ty * 8];
                *(float4*)&a[4] = *(const float4*)&As[k][ty * 8 + 4];
                *(float4*)&b[0] = *(const float4*)&Bs[k][tx * 8];
                *(float4*)&b[4] = *(const float4*)&Bs[k][tx * 8 + 4];
#pragma unroll
                for (int i = 0; i < 8; i++)
#pragma unroll
                    for (int j = 0; j < 8; j++) acc[i][j] += a[i] * b[j];
            }
            __syncthreads();
        }
    }

#pragma unroll
    for (int i = 0; i < 8; i++) {
        const int row = brow + ty * 8 + i;
        if (row >= Mstore) continue;
#pragma unroll
        for (int j = 0; j < 8; j += 4) {
            const int col = bcol + tx * 8 + j;
            float4 v;
            v.x = acc[i][j + 0] + bias[col + 0];
            v.y = acc[i][j + 1] + bias[col + 1];
            v.z = acc[i][j + 2] + bias[col + 2];
            v.w = acc[i][j + 3] + bias[col + 3];
            if (RELU) {
                v.x = fmaxf(v.x, 0.f);
                v.y = fmaxf(v.y, 0.f);
                v.z = fmaxf(v.z, 0.f);
                v.w = fmaxf(v.w, 0.f);
            }
            *(float4*)&C[(size_t)row * ldc + col] = v;
        }
    }
}

__global__ void __launch_bounds__(256)
k_gemm1(const float* __restrict__ B1, const float* __restrict__ B2,
        const float* __restrict__ bias) {
    gemm_impl<true>(g_mean1, 128, B1, g_xp, 128, B2, bias, g_h, 256, 256, N_NODES);
}

__global__ void __launch_bounds__(256)
k_gemm2(const float* __restrict__ B1, const float* __restrict__ B2,
        const float* __restrict__ bias, float* __restrict__ C) {
    gemm_impl<false>(g_mean2, 256, B1, g_h, 256, B2, bias, C, 128, 128, N_NODES);
}

// ---------------- launch -------------------------------------------------------
extern "C" void kernel_launch(void* const* d_in, const int* in_sizes, int n_in,
                              void* d_out, int out_size) {
    const float* x    = (const float*)d_in[0];
    const int*   ei32 = (const int*)d_in[1];      // int32 or int64 [2,E]; detected on device
    const float* w1_l = (const float*)d_in[2];    // [128,256]
    const float* b1_l = (const float*)d_in[3];    // [256]
    const float* w1_r = (const float*)d_in[4];    // [128,256]
    const float* w2_l = (const float*)d_in[5];    // [256,128]
    const float* b2_l = (const float*)d_in[6];    // [128]
    const float* w2_r = (const float*)d_in[7];    // [256,128]
    float* out = (float*)d_out;

    // 0) edge dtype detect + convert to int32 src/dst
    k_detect<<<1, 1>>>(ei32);
    k_conv<<<(N_EDGES + 255) / 256, 256>>>(ei32);

    // 1) CSR build + padded x copy
    k_zero_cnt<<<(N_NODES + 255) / 256, 256>>>();
    k_hist<<<(N_EDGES + 255) / 256, 256>>>();
    k_scan<<<1, 1024>>>();
    k_scatter<<<(N_EDGES + 255) / 256, 256>>>();
    k_copy_x<<<(N_NODES * 128 / 4 + 255) / 256, 256>>>(x);

    // 2) layer 1: mean-agg then fused dual-GEMM + bias + ReLU
    k_agg1<<<(N_NODES + 7) / 8, 256>>>();
    {
        dim3 grid(256 / 128, NPAD / 128);   // (2, 391)
        k_gemm1<<<grid, 256>>>(w1_l, w1_r, b1_l);
    }

    // 3) layer 2
    k_agg2<<<(N_NODES + 7) / 8, 256>>>();
    {
        dim3 grid(128 / 128, NPAD / 128);   // (1, 391)
        k_gemm2<<<grid, 256>>>(w2_l, w2_r, b2_l, out);
    }
}

// round 5
// speedup vs baseline: 1.6079x; 1.6079x over previous
#include <cuda_runtime.h>
#include <cuda_bf16.h>
#include <cstdint>

#define N_NODES 50000
#define N_EDGES 640000
#define NPAD    50048      // 391 * 128

// ---------------- device scratch ----------------------------------------------
__device__ alignas(16)  int   g_is64;
__device__ alignas(16)  int   g_src[N_EDGES];
__device__ alignas(16)  int   g_dst[N_EDGES];
__device__ alignas(16)  int   g_cnt[N_NODES];
__device__ alignas(16)  int   g_rowptr[N_NODES + 1];
__device__ alignas(16)  int   g_fill[N_NODES];
__device__ alignas(16)  int   g_perm[N_EDGES];
__device__ alignas(256) float g_xp[(size_t)NPAD * 128];
__device__ alignas(256) float g_mean1[(size_t)NPAD * 128];
__device__ alignas(256) float g_h[(size_t)NPAD * 256];
__device__ alignas(256) float g_mean2[(size_t)NPAD * 256];

// ---------------- edge dtype detection + conversion ---------------------------
__global__ void k_detect(const int* __restrict__ ei32) {
    int is64 = 1;
    for (int i = 0; i < 64; i++)
        if (ei32[2 * i + 1] != 0) { is64 = 0; break; }
    g_is64 = is64;
}

__global__ void k_conv(const int* __restrict__ ei32) {
    int i = blockIdx.x * blockDim.x + threadIdx.x;
    if (i >= N_EDGES) return;
    int s, d;
    if (g_is64) {
        s = ei32[2 * i];
        d = ei32[2 * (N_EDGES + i)];
    } else {
        s = ei32[i];
        d = ei32[N_EDGES + i];
    }
    g_src[i] = min(max(s, 0), N_NODES - 1);
    g_dst[i] = min(max(d, 0), N_NODES - 1);
}

// ---------------- CSR construction --------------------------------------------
__global__ void k_zero_cnt() {
    int i = blockIdx.x * blockDim.x + threadIdx.x;
    if (i < N_NODES) g_cnt[i] = 0;
}

__global__ void k_hist() {
    int i = blockIdx.x * blockDim.x + threadIdx.x;
    if (i < N_EDGES) atomicAdd(&g_cnt[g_dst[i]], 1);
}

__global__ void k_scan() {
    __shared__ int s[1024];
    const int t = threadIdx.x;
    const int chunk = (N_NODES + 1023) / 1024;
    const int beg = t * chunk;
    const int end = min(beg + chunk, N_NODES);
    int sum = 0;
    for (int i = beg; i < end; i++) sum += g_cnt[i];
    s[t] = sum;
    __syncthreads();
    for (int off = 1; off < 1024; off <<= 1) {
        int v = 0;
        if (t >= off) v = s[t - off];
        __syncthreads();
        if (t >= off) s[t] += v;
        __syncthreads();
    }
    int run = (t == 0) ? 0 : s[t - 1];
    for (int i = beg; i < end; i++) {
        g_rowptr[i] = run;
        g_fill[i]   = run;
        run += g_cnt[i];
    }
    if (t == 0) g_rowptr[N_NODES] = N_EDGES;
}

__global__ void k_scatter() {
    int i = blockIdx.x * blockDim.x + threadIdx.x;
    if (i < N_EDGES) {
        int pos = atomicAdd(&g_fill[g_dst[i]], 1);
        g_perm[pos] = g_src[i];
    }
}

__global__ void k_copy_x(const float* __restrict__ x) {
    int i = blockIdx.x * blockDim.x + threadIdx.x;
    const int n4 = N_NODES * 128 / 4;
    if (i < n4) ((float4*)g_xp)[i] = ((const float4*)x)[i];
}

// ---------------- mean aggregation: one warp per node -------------------------
template <int CH>
__device__ __forceinline__ void agg_impl(const float* __restrict__ feat,
                                         float* __restrict__ out) {
    const int gwarp = (blockIdx.x * blockDim.x + threadIdx.x) >> 5;
    const int lane  = threadIdx.x & 31;
    if (gwarp >= N_NODES) return;
    const int beg = g_rowptr[gwarp];
    const int end = g_rowptr[gwarp + 1];
    constexpr int F4 = CH / 128;
    float4 acc[F4];
#pragma unroll
    for (int f = 0; f < F4; f++) acc[f] = make_float4(0.f, 0.f, 0.f, 0.f);
    for (int e = beg; e < end; e++) {
        const int s = g_perm[e];
        const float4* p = (const float4*)(feat + (size_t)s * CH);
#pragma unroll
        for (int f = 0; f < F4; f++) {
            float4 v = p[lane + f * 32];
            acc[f].x += v.x; acc[f].y += v.y; acc[f].z += v.z; acc[f].w += v.w;
        }
    }
    const float inv = 1.0f / (float)max(end - beg, 1);
    float4* o = (float4*)(out + (size_t)gwarp * CH);
#pragma unroll
    for (int f = 0; f < F4; f++) {
        float4 v = acc[f];
        v.x *= inv; v.y *= inv; v.z *= inv; v.w *= inv;
        o[lane + f * 32] = v;
    }
}

__global__ void k_agg1() { agg_impl<128>(g_xp, g_mean1); }
__global__ void k_agg2() { agg_impl<256>(g_h,  g_mean2); }

// ---------------- tf32 tensor-core dual-GEMM ----------------------------------
// C[NPAD, N] = A1@B1 + A2@B2 + bias (+ReLU); A row-major [NPAD,K], B [K,N].
// Block: 128x128, 8 warps (2x4), warp tile 64x32 via 4x4 m16n8k8 mma.

__device__ __forceinline__ uint32_t f2tf32(float f) {
    uint32_t r;
    asm("cvt.rna.tf32.f32 %0, %1;" : "=r"(r) : "f"(f));
    return r;
}

__device__ __forceinline__ void mma_tf32(float d[4], uint32_t a0, uint32_t a1,
                                         uint32_t a2, uint32_t a3,
                                         uint32_t b0, uint32_t b1) {
    asm volatile(
        "mma.sync.aligned.m16n8k8.row.col.f32.tf32.tf32.f32 "
        "{%0,%1,%2,%3}, {%4,%5,%6,%7}, {%8,%9}, {%0,%1,%2,%3};"
        : "+f"(d[0]), "+f"(d[1]), "+f"(d[2]), "+f"(d[3])
        : "r"(a0), "r"(a1), "r"(a2), "r"(a3), "r"(b0), "r"(b1));
}

template <bool RELU>
__device__ __forceinline__ void
tgemm(const float* __restrict__ A1, int K1, const float* __restrict__ B1,
      const float* __restrict__ A2, int K2, const float* __restrict__ B2,
      const float* __restrict__ bias,
      float* __restrict__ C, int ldc, int Ncols, int Mstore) {
    constexpr int BM = 128, BN = 128, BK = 32;
    constexpr int AS = 36;    // A smem row stride (floats): conflict-free frags
    constexpr int BS = 136;   // B smem row stride (floats): conflict-free frags
    __shared__ uint32_t As[BM * AS];
    __shared__ uint32_t Bs[BK * BS];

    const int tid  = threadIdx.x;
    const int wid  = tid >> 5;
    const int lane = tid & 31;
    const int wm = wid & 1;          // 0..1 -> 64-row slabs
    const int wn = wid >> 1;         // 0..3 -> 32-col slabs
    const int brow = blockIdx.y * BM;
    const int bcol = blockIdx.x * BN;

    float acc[4][4][4];
#pragma unroll
    for (int mt = 0; mt < 4; mt++)
#pragma unroll
        for (int nt = 0; nt < 4; nt++)
#pragma unroll
            for (int r = 0; r < 4; r++) acc[mt][nt][r] = 0.f;

#pragma unroll 1
    for (int pass = 0; pass < 2; pass++) {
        const float* A = pass ? A2 : A1;
        const float* B = pass ? B2 : B1;
        const int K   = pass ? K2 : K1;
#pragma unroll 1
        for (int k0 = 0; k0 < K; k0 += BK) {
            // stage A tile: 128 x 32 (8 float4 per row), 4 float4 per thread
#pragma unroll
            for (int p = 0; p < 4; p++) {
                const int idx = tid + p * 256;
                const int row = idx >> 3;
                const int c4  = (idx & 7) << 2;
                float4 v = *(const float4*)&A[(size_t)(brow + row) * K + k0 + c4];
                uint32_t* d = &As[row * AS + c4];
                d[0] = f2tf32(v.x); d[1] = f2tf32(v.y);
                d[2] = f2tf32(v.z); d[3] = f2tf32(v.w);
            }
            // stage B tile: 32 x 128 (32 float4 per row), 4 float4 per thread
#pragma unroll
            for (int p = 0; p < 4; p++) {
                const int idx = tid + p * 256;
                const int row = idx >> 5;
                const int c4  = (idx & 31) << 2;
                float4 v = *(const float4*)&B[(size_t)(k0 + row) * Ncols + bcol + c4];
                uint32_t* d = &Bs[row * BS + c4];
                d[0] = f2tf32(v.x); d[1] = f2tf32(v.y);
                d[2] = f2tf32(v.z); d[3] = f2tf32(v.w);
            }
            __syncthreads();

#pragma unroll
            for (int ks = 0; ks < 4; ks++) {
                const int kk = ks * 8;
                uint32_t af[4][4];
#pragma unroll
                for (int mt = 0; mt < 4; mt++) {
                    const int r = wm * 64 + mt * 16 + (lane >> 2);
                    const int c = kk + (lane & 3);
                    af[mt][0] = As[r * AS + c];
                    af[mt][1] = As[(r + 8) * AS + c];
                    af[mt][2] = As[r * AS + c + 4];
                    af[mt][3] = As[(r + 8) * AS + c + 4];
                }
                uint32_t bf[4][2];
#pragma unroll
                for (int nt = 0; nt < 4; nt++) {
                    const int n = wn * 32 + nt * 8 + (lane >> 2);
                    const int k = kk + (lane & 3);
                    bf[nt][0] = Bs[k * BS + n];
                    bf[nt][1] = Bs[(k + 4) * BS + n];
                }
#pragma unroll
                for (int mt = 0; mt < 4; mt++)
#pragma unroll
                    for (int nt = 0; nt < 4; nt++)
                        mma_tf32(acc[mt][nt], af[mt][0], af[mt][1], af[mt][2],
                                 af[mt][3], bf[nt][0], bf[nt][1]);
            }
            __syncthreads();
        }
    }

    // epilogue: bias (+ReLU), guarded float2 stores
#pragma unroll
    for (int nt = 0; nt < 4; nt++) {
        const int col = bcol + wn * 32 + nt * 8 + ((lane & 3) << 1);
        const float bx = bias[col];
        const float by = bias[col + 1];
#pragma unroll
        for (int mt = 0; mt < 4; mt++) {
            const int row0 = brow + wm * 64 + mt * 16 + (lane >> 2);
            float2 v0, v1;
            v0.x = acc[mt][nt][0] + bx;  v0.y = acc[mt][nt][1] + by;
            v1.x = acc[mt][nt][2] + bx;  v1.y = acc[mt][nt][3] + by;
            if (RELU) {
                v0.x = fmaxf(v0.x, 0.f); v0.y = fmaxf(v0.y, 0.f);
                v1.x = fmaxf(v1.x, 0.f); v1.y = fmaxf(v1.y, 0.f);
            }
            if (row0 < Mstore)
                *(float2*)&C[(size_t)row0 * ldc + col] = v0;
            if (row0 + 8 < Mstore)
                *(float2*)&C[(size_t)(row0 + 8) * ldc + col] = v1;
        }
    }
}

__global__ void __launch_bounds__(256)
k_gemm1(const float* __restrict__ B1, const float* __restrict__ B2,
        const float* __restrict__ bias) {
    tgemm<true>(g_mean1, 128, B1, g_xp, 128, B2, bias, g_h, 256, 256, N_NODES);
}

__global__ void __launch_bounds__(256)
k_gemm2(const float* __restrict__ B1, const float* __restrict__ B2,
        const float* __restrict__ bias, float* __restrict__ C) {
    tgemm<false>(g_mean2, 256, B1, g_h, 256, B2, bias, C, 128, 128, N_NODES);
}

// ---------------- launch -------------------------------------------------------
extern "C" void kernel_launch(void* const* d_in, const int* in_sizes, int n_in,
                              void* d_out, int out_size) {
    const float* x    = (const float*)d_in[0];
    const int*   ei32 = (const int*)d_in[1];
    const float* w1_l = (const float*)d_in[2];
    const float* b1_l = (const float*)d_in[3];
    const float* w1_r = (const float*)d_in[4];
    const float* w2_l = (const float*)d_in[5];
    const float* b2_l = (const float*)d_in[6];
    const float* w2_r = (const float*)d_in[7];
    float* out = (float*)d_out;

    k_detect<<<1, 1>>>(ei32);
    k_conv<<<(N_EDGES + 255) / 256, 256>>>(ei32);

    k_zero_cnt<<<(N_NODES + 255) / 256, 256>>>();
    k_hist<<<(N_EDGES + 255) / 256, 256>>>();
    k_scan<<<1, 1024>>>();
    k_scatter<<<(N_EDGES + 255) / 256, 256>>>();
    k_copy_x<<<(N_NODES * 128 / 4 + 255) / 256, 256>>>(x);

    k_agg1<<<(N_NODES + 7) / 8, 256>>>();
    {
        dim3 grid(2, NPAD / 128);
        k_gemm1<<<grid, 256>>>(w1_l, w1_r, b1_l);
    }

    k_agg2<<<(N_NODES + 7) / 8, 256>>>();
    {
        dim3 grid(1, NPAD / 128);
        k_gemm2<<<grid, 256>>>(w2_l, w2_r, b2_l, out);
    }
}

// round 6
// speedup vs baseline: 1.8103x; 1.1259x over previous
#include <cuda_runtime.h>
#include <cuda_bf16.h>
#include <cstdint>

#define N_NODES 50000
#define N_EDGES 640000
#define NPAD    50048      // 391 * 128

// ---------------- device scratch ----------------------------------------------
__device__ alignas(16)  int   g_is64;
__device__ alignas(16)  int   g_src[N_EDGES];
__device__ alignas(16)  int   g_dst[N_EDGES];
__device__ alignas(16)  int   g_cnt[N_NODES];
__device__ alignas(16)  int   g_rowptr[N_NODES + 1];
__device__ alignas(16)  int   g_fill[N_NODES];
__device__ alignas(16)  int   g_perm[N_EDGES];
__device__ alignas(256) float g_mean1[(size_t)NPAD * 128];
__device__ alignas(256) float g_h[(size_t)NPAD * 256];
__device__ alignas(256) float g_pr[(size_t)NPAD * 256];   // [p | r] for layer 2

// ---------------- edge dtype detection ----------------------------------------
__global__ void k_detect(const int* __restrict__ ei32) {
    int is64 = 1;
    for (int i = 0; i < 64; i++)
        if (ei32[2 * i + 1] != 0) { is64 = 0; break; }
    g_is64 = is64;
}

__global__ void k_zero_cnt() {
    int i = blockIdx.x * blockDim.x + threadIdx.x;
    if (i < N_NODES) g_cnt[i] = 0;
}

// fused: decode edge (int32/int64), clamp, store src/dst, histogram dst
__global__ void k_conv_hist(const int* __restrict__ ei32) {
    int i = blockIdx.x * blockDim.x + threadIdx.x;
    if (i >= N_EDGES) return;
    int s, d;
    if (g_is64) {
        s = ei32[2 * i];
        d = ei32[2 * (N_EDGES + i)];
    } else {
        s = ei32[i];
        d = ei32[N_EDGES + i];
    }
    s = min(max(s, 0), N_NODES - 1);
    d = min(max(d, 0), N_NODES - 1);
    g_src[i] = s;
    g_dst[i] = d;
    atomicAdd(&g_cnt[d], 1);
}

__global__ void k_scan() {
    __shared__ int s[1024];
    const int t = threadIdx.x;
    const int chunk = (N_NODES + 1023) / 1024;
    const int beg = t * chunk;
    const int end = min(beg + chunk, N_NODES);
    int sum = 0;
    for (int i = beg; i < end; i++) sum += g_cnt[i];
    s[t] = sum;
    __syncthreads();
    for (int off = 1; off < 1024; off <<= 1) {
        int v = 0;
        if (t >= off) v = s[t - off];
        __syncthreads();
        if (t >= off) s[t] += v;
        __syncthreads();
    }
    int run = (t == 0) ? 0 : s[t - 1];
    for (int i = beg; i < end; i++) {
        g_rowptr[i] = run;
        g_fill[i]   = run;
        run += g_cnt[i];
    }
    if (t == 0) g_rowptr[N_NODES] = N_EDGES;
}

__global__ void k_scatter() {
    int i = blockIdx.x * blockDim.x + threadIdx.x;
    if (i < N_EDGES) {
        int pos = atomicAdd(&g_fill[g_dst[i]], 1);
        g_perm[pos] = g_src[i];
    }
}

// ---------------- layer-1 aggregation: warp per node, gather x (128ch) --------
__global__ void k_agg1(const float* __restrict__ x) {
    const int node = (blockIdx.x * blockDim.x + threadIdx.x) >> 5;
    const int lane = threadIdx.x & 31;
    if (node >= N_NODES) return;
    const int beg = g_rowptr[node];
    const int end = g_rowptr[node + 1];
    float4 acc = make_float4(0.f, 0.f, 0.f, 0.f);
    for (int e = beg; e < end; e++) {
        const int s = g_perm[e];
        float4 v = ((const float4*)(x + (size_t)s * 128))[lane];
        acc.x += v.x; acc.y += v.y; acc.z += v.z; acc.w += v.w;
    }
    const float inv = 1.0f / (float)max(end - beg, 1);
    acc.x *= inv; acc.y *= inv; acc.z *= inv; acc.w *= inv;
    ((float4*)(g_mean1 + (size_t)node * 128))[lane] = acc;
}

// ---------------- layer-2 aggregation + epilogue -------------------------------
// out[i] = mean-gather of p (pr cols 0..127) + r (pr cols 128..255) + bias
__global__ void k_agg2b(const float* __restrict__ bias, float* __restrict__ out) {
    const int node = (blockIdx.x * blockDim.x + threadIdx.x) >> 5;
    const int lane = threadIdx.x & 31;
    if (node >= N_NODES) return;
    const int beg = g_rowptr[node];
    const int end = g_rowptr[node + 1];
    float4 acc = make_float4(0.f, 0.f, 0.f, 0.f);
    for (int e = beg; e < end; e++) {
        const int s = g_perm[e];
        float4 v = ((const float4*)(g_pr + (size_t)s * 256))[lane];
        acc.x += v.x; acc.y += v.y; acc.z += v.z; acc.w += v.w;
    }
    const float inv = 1.0f / (float)max(end - beg, 1);
    float4 r = ((const float4*)(g_pr + (size_t)node * 256 + 128))[lane];
    float4 b = ((const float4*)bias)[lane];
    float4 o;
    o.x = acc.x * inv + r.x + b.x;
    o.y = acc.y * inv + r.y + b.y;
    o.z = acc.z * inv + r.z + b.z;
    o.w = acc.w * inv + r.w + b.w;
    ((float4*)(out + (size_t)node * 128))[lane] = o;
}

// ---------------- tf32 tensor-core GEMM ----------------------------------------
__device__ __forceinline__ uint32_t f2tf32(float f) {
    uint32_t r;
    asm("cvt.rna.tf32.f32 %0, %1;" : "=r"(r) : "f"(f));
    return r;
}

__device__ __forceinline__ void mma_tf32(float d[4], uint32_t a0, uint32_t a1,
                                         uint32_t a2, uint32_t a3,
                                         uint32_t b0, uint32_t b1) {
    asm volatile(
        "mma.sync.aligned.m16n8k8.row.col.f32.tf32.tf32.f32 "
        "{%0,%1,%2,%3}, {%4,%5,%6,%7}, {%8,%9}, {%0,%1,%2,%3};"
        : "+f"(d[0]), "+f"(d[1]), "+f"(d[2]), "+f"(d[3])
        : "r"(a0), "r"(a1), "r"(a2), "r"(a3), "r"(b0), "r"(b1));
}

// Block 128x128, 8 warps (2x4), warp tile 64x32 via 4x4 m16n8k8.
// A row-major [*, K] with row clamp to Mclamp-1 (no padding buffers needed).
// B row-major [K, ldb], tile columns at bofs. Optional second (A2,B2,K2) pass
// accumulates (concat-K). Optional bias; optional ReLU.
template <bool RELU>
__device__ __forceinline__ void
tgemm(const float* __restrict__ A1, int K1, const float* __restrict__ B1,
      const float* __restrict__ A2, int K2, const float* __restrict__ B2,
      int ldb, int bofs, const float* __restrict__ bias,
      float* __restrict__ C, int ldc, int Mstore, int Mclamp) {
    constexpr int BM = 128, BK = 32;
    constexpr int AS = 36;
    constexpr int BS = 136;
    __shared__ uint32_t As[BM * AS];
    __shared__ uint32_t Bs[BK * BS];

    const int tid  = threadIdx.x;
    const int wid  = tid >> 5;
    const int lane = tid & 31;
    const int wm = wid & 1;
    const int wn = wid >> 1;
    const int brow = blockIdx.y * BM;

    float acc[4][4][4];
#pragma unroll
    for (int mt = 0; mt < 4; mt++)
#pragma unroll
        for (int nt = 0; nt < 4; nt++)
#pragma unroll
            for (int r = 0; r < 4; r++) acc[mt][nt][r] = 0.f;

#pragma unroll 1
    for (int pass = 0; pass < 2; pass++) {
        const float* A = pass ? A2 : A1;
        const float* B = pass ? B2 : B1;
        const int K   = pass ? K2 : K1;
#pragma unroll 1
        for (int k0 = 0; k0 < K; k0 += BK) {
            // stage A tile: 128 x 32, rows clamped into valid range
#pragma unroll
            for (int p = 0; p < 4; p++) {
                const int idx = tid + p * 256;
                const int row = idx >> 3;
                const int c4  = (idx & 7) << 2;
                const int rg  = min(brow + row, Mclamp - 1);
                float4 v = *(const float4*)&A[(size_t)rg * K + k0 + c4];
                uint32_t* d = &As[row * AS + c4];
                d[0] = f2tf32(v.x); d[1] = f2tf32(v.y);
                d[2] = f2tf32(v.z); d[3] = f2tf32(v.w);
            }
            // stage B tile: 32 x 128
#pragma unroll
            for (int p = 0; p < 4; p++) {
                const int idx = tid + p * 256;
                const int row = idx >> 5;
                const int c4  = (idx & 31) << 2;
                float4 v = *(const float4*)&B[(size_t)(k0 + row) * ldb + bofs + c4];
                uint32_t* d = &Bs[row * BS + c4];
                d[0] = f2tf32(v.x); d[1] = f2tf32(v.y);
                d[2] = f2tf32(v.z); d[3] = f2tf32(v.w);
            }
            __syncthreads();

#pragma unroll
            for (int ks = 0; ks < 4; ks++) {
                const int kk = ks * 8;
                uint32_t af[4][4];
#pragma unroll
                for (int mt = 0; mt < 4; mt++) {
                    const int r = wm * 64 + mt * 16 + (lane >> 2);
                    const int c = kk + (lane & 3);
                    af[mt][0] = As[r * AS + c];
                    af[mt][1] = As[(r + 8) * AS + c];
                    af[mt][2] = As[r * AS + c + 4];
                    af[mt][3] = As[(r + 8) * AS + c + 4];
                }
                uint32_t bf[4][2];
#pragma unroll
                for (int nt = 0; nt < 4; nt++) {
                    const int n = wn * 32 + nt * 8 + (lane >> 2);
                    const int k = kk + (lane & 3);
                    bf[nt][0] = Bs[k * BS + n];
                    bf[nt][1] = Bs[(k + 4) * BS + n];
                }
#pragma unroll
                for (int mt = 0; mt < 4; mt++)
#pragma unroll
                    for (int nt = 0; nt < 4; nt++)
                        mma_tf32(acc[mt][nt], af[mt][0], af[mt][1], af[mt][2],
                                 af[mt][3], bf[nt][0], bf[nt][1]);
            }
            __syncthreads();
        }
    }

    const int bcolC = blockIdx.x * 128;
#pragma unroll
    for (int nt = 0; nt < 4; nt++) {
        const int col = bcolC + wn * 32 + nt * 8 + ((lane & 3) << 1);
        float bx = 0.f, by = 0.f;
        if (bias) { bx = bias[col]; by = bias[col + 1]; }
#pragma unroll
        for (int mt = 0; mt < 4; mt++) {
            const int row0 = brow + wm * 64 + mt * 16 + (lane >> 2);
            float2 v0, v1;
            v0.x = acc[mt][nt][0] + bx;  v0.y = acc[mt][nt][1] + by;
            v1.x = acc[mt][nt][2] + bx;  v1.y = acc[mt][nt][3] + by;
            if (RELU) {
                v0.x = fmaxf(v0.x, 0.f); v0.y = fmaxf(v0.y, 0.f);
                v1.x = fmaxf(v1.x, 0.f); v1.y = fmaxf(v1.y, 0.f);
            }
            if (row0 < Mstore)
                *(float2*)&C[(size_t)row0 * ldc + col] = v0;
            if (row0 + 8 < Mstore)
                *(float2*)&C[(size_t)(row0 + 8) * ldc + col] = v1;
        }
    }
}

// layer 1: h = relu([mean1 | x] @ [w1_l ; w1_r] + b1), N=256, dual-K
__global__ void __launch_bounds__(256)
k_gemm1(const float* __restrict__ x,
        const float* __restrict__ B1, const float* __restrict__ B2,
        const float* __restrict__ bias) {
    const int bofs = blockIdx.x * 128;
    tgemm<true>(g_mean1, 128, B1, x, 128, B2, 256, bofs, bias,
                g_h, 256, N_NODES, N_NODES);
}

// layer 2 (reordered): pr = h @ [w2_l | w2_r]; block.x selects the weight
__global__ void __launch_bounds__(256)
k_gemm2(const float* __restrict__ w2l, const float* __restrict__ w2r) {
    const float* B = blockIdx.x ? w2r : w2l;
    tgemm<false>(g_h, 256, B, nullptr, 0, nullptr, 128, 0, nullptr,
                 g_pr, 256, N_NODES, N_NODES);
}

// ---------------- launch -------------------------------------------------------
extern "C" void kernel_launch(void* const* d_in, const int* in_sizes, int n_in,
                              void* d_out, int out_size) {
    const float* x    = (const float*)d_in[0];
    const int*   ei32 = (const int*)d_in[1];
    const float* w1_l = (const float*)d_in[2];
    const float* b1_l = (const float*)d_in[3];
    const float* w1_r = (const float*)d_in[4];
    const float* w2_l = (const float*)d_in[5];
    const float* b2_l = (const float*)d_in[6];
    const float* w2_r = (const float*)d_in[7];
    float* out = (float*)d_out;

    k_detect<<<1, 1>>>(ei32);
    k_zero_cnt<<<(N_NODES + 255) / 256, 256>>>();
    k_conv_hist<<<(N_EDGES + 255) / 256, 256>>>(ei32);
    k_scan<<<1, 1024>>>();
    k_scatter<<<(N_EDGES + 255) / 256, 256>>>();

    k_agg1<<<(N_NODES + 7) / 8, 256>>>(x);
    {
        dim3 grid(2, NPAD / 128);
        k_gemm1<<<grid, 256>>>(x, w1_l, w1_r, b1_l);
    }
    {
        dim3 grid(2, NPAD / 128);
        k_gemm2<<<grid, 256>>>(w2_l, w2_r);
    }
    k_agg2b<<<(N_NODES + 7) / 8, 256>>>(b2_l, out);
}

// round 7
// speedup vs baseline: 2.4114x; 1.3320x over previous
#include <cuda_runtime.h>
#include <cuda_bf16.h>
#include <cstdint>

#define N_NODES 50000
#define N_EDGES 640000
#define NPAD    50048      // 391 * 128
#define SCAN_BLK 512
#define SCAN_NBLK ((N_NODES + SCAN_BLK - 1) / SCAN_BLK)   // 98

// ---------------- device scratch ----------------------------------------------
__device__ alignas(16)  int   g_is64;
__device__ alignas(16)  int   g_src[N_EDGES];
__device__ alignas(16)  int   g_dst[N_EDGES];
__device__ alignas(16)  int   g_cnt[N_NODES];
__device__ alignas(16)  int   g_rowptr[N_NODES + 1];
__device__ alignas(16)  int   g_fill[N_NODES];
__device__ alignas(16)  int   g_perm[N_EDGES];
__device__ alignas(16)  int   g_bsum[SCAN_NBLK];
__device__ alignas(16)  int   g_boff[SCAN_NBLK];
__device__ alignas(256) float g_mean1[(size_t)NPAD * 128];
__device__ alignas(256) float g_h[(size_t)NPAD * 256];
__device__ alignas(256) float g_pr[(size_t)NPAD * 256];   // [p | r] for layer 2

// ---------------- edge dtype detection ----------------------------------------
__global__ void k_detect(const int* __restrict__ ei32) {
    int is64 = 1;
    for (int i = 0; i < 64; i++)
        if (ei32[2 * i + 1] != 0) { is64 = 0; break; }
    g_is64 = is64;
}

__global__ void k_zero_cnt() {
    int i = blockIdx.x * blockDim.x + threadIdx.x;
    if (i < N_NODES) g_cnt[i] = 0;
}

// fused: decode edge (int32/int64), clamp, store src/dst, histogram dst
__global__ void k_conv_hist(const int* __restrict__ ei32) {
    int i = blockIdx.x * blockDim.x + threadIdx.x;
    if (i >= N_EDGES) return;
    int s, d;
    if (g_is64) {
        s = ei32[2 * i];
        d = ei32[2 * (N_EDGES + i)];
    } else {
        s = ei32[i];
        d = ei32[N_EDGES + i];
    }
    s = min(max(s, 0), N_NODES - 1);
    d = min(max(d, 0), N_NODES - 1);
    g_src[i] = s;
    g_dst[i] = d;
    atomicAdd(&g_cnt[d], 1);
}

// ---------------- two-level parallel scan --------------------------------------
// stage 1: per-block exclusive scan of 512 counts; emit block total
__global__ void k_scan_blk() {
    __shared__ int s[SCAN_BLK];
    const int t = threadIdx.x;
    const int i = blockIdx.x * SCAN_BLK + t;
    const int v = (i < N_NODES) ? g_cnt[i] : 0;
    s[t] = v;
    __syncthreads();
#pragma unroll
    for (int off = 1; off < SCAN_BLK; off <<= 1) {
        int u = 0;
        if (t >= off) u = s[t - off];
        __syncthreads();
        if (t >= off) s[t] += u;
        __syncthreads();
    }
    if (i < N_NODES) g_rowptr[i] = s[t] - v;          // within-block exclusive
    if (t == SCAN_BLK - 1) g_bsum[blockIdx.x] = s[t]; // block total
}

// stage 2: exclusive scan of the 98 block sums (one tiny block)
__global__ void k_scan_top() {
    __shared__ int s[128];
    const int t = threadIdx.x;
    const int v = (t < SCAN_NBLK) ? g_bsum[t] : 0;
    s[t] = v;
    __syncthreads();
#pragma unroll
    for (int off = 1; off < 128; off <<= 1) {
        int u = 0;
        if (t >= off) u = s[t - off];
        __syncthreads();
        if (t >= off) s[t] += u;
        __syncthreads();
    }
    if (t < SCAN_NBLK) g_boff[t] = s[t] - v;
}

// stage 3: add block offsets; finalize rowptr + fill
__global__ void k_scan_add() {
    const int i = blockIdx.x * SCAN_BLK + threadIdx.x;
    if (i < N_NODES) {
        const int r = g_rowptr[i] + g_boff[blockIdx.x];
        g_rowptr[i] = r;
        g_fill[i]   = r;
    }
    if (i == 0) g_rowptr[N_NODES] = N_EDGES;
}

__global__ void k_scatter() {
    int i = blockIdx.x * blockDim.x + threadIdx.x;
    if (i < N_EDGES) {
        int pos = atomicAdd(&g_fill[g_dst[i]], 1);
        g_perm[pos] = g_src[i];
    }
}

// ---------------- layer-1 aggregation: warp per node, gather x (128ch) --------
__global__ void k_agg1(const float* __restrict__ x) {
    const int node = (blockIdx.x * blockDim.x + threadIdx.x) >> 5;
    const int lane = threadIdx.x & 31;
    if (node >= N_NODES) return;
    const int beg = g_rowptr[node];
    const int end = g_rowptr[node + 1];
    float4 acc = make_float4(0.f, 0.f, 0.f, 0.f);
    for (int e = beg; e < end; e++) {
        const int s = g_perm[e];
        float4 v = ((const float4*)(x + (size_t)s * 128))[lane];
        acc.x += v.x; acc.y += v.y; acc.z += v.z; acc.w += v.w;
    }
    const float inv = 1.0f / (float)max(end - beg, 1);
    acc.x *= inv; acc.y *= inv; acc.z *= inv; acc.w *= inv;
    ((float4*)(g_mean1 + (size_t)node * 128))[lane] = acc;
}

// ---------------- layer-2 aggregation + epilogue -------------------------------
__global__ void k_agg2b(const float* __restrict__ bias, float* __restrict__ out) {
    const int node = (blockIdx.x * blockDim.x + threadIdx.x) >> 5;
    const int lane = threadIdx.x & 31;
    if (node >= N_NODES) return;
    const int beg = g_rowptr[node];
    const int end = g_rowptr[node + 1];
    float4 acc = make_float4(0.f, 0.f, 0.f, 0.f);
    for (int e = beg; e < end; e++) {
        const int s = g_perm[e];
        float4 v = ((const float4*)(g_pr + (size_t)s * 256))[lane];
        acc.x += v.x; acc.y += v.y; acc.z += v.z; acc.w += v.w;
    }
    const float inv = 1.0f / (float)max(end - beg, 1);
    float4 r = ((const float4*)(g_pr + (size_t)node * 256 + 128))[lane];
    float4 b = ((const float4*)bias)[lane];
    float4 o;
    o.x = acc.x * inv + r.x + b.x;
    o.y = acc.y * inv + r.y + b.y;
    o.z = acc.z * inv + r.z + b.z;
    o.w = acc.w * inv + r.w + b.w;
    ((float4*)(out + (size_t)node * 128))[lane] = o;
}

// ---------------- tf32 tensor-core GEMM ----------------------------------------
__device__ __forceinline__ uint32_t f2tf32(float f) {
    uint32_t r;
    asm("cvt.rna.tf32.f32 %0, %1;" : "=r"(r) : "f"(f));
    return r;
}

__device__ __forceinline__ void mma_tf32(float d[4], uint32_t a0, uint32_t a1,
                                         uint32_t a2, uint32_t a3,
                                         uint32_t b0, uint32_t b1) {
    asm volatile(
        "mma.sync.aligned.m16n8k8.row.col.f32.tf32.tf32.f32 "
        "{%0,%1,%2,%3}, {%4,%5,%6,%7}, {%8,%9}, {%0,%1,%2,%3};"
        : "+f"(d[0]), "+f"(d[1]), "+f"(d[2]), "+f"(d[3])
        : "r"(a0), "r"(a1), "r"(a2), "r"(a3), "r"(b0), "r"(b1));
}

template <bool RELU>
__device__ __forceinline__ void
tgemm(const float* __restrict__ A1, int K1, const float* __restrict__ B1,
      const float* __restrict__ A2, int K2, const float* __restrict__ B2,
      int ldb, int bofs, const float* __restrict__ bias,
      float* __restrict__ C, int ldc, int Mstore, int Mclamp) {
    constexpr int BM = 128, BK = 32;
    constexpr int AS = 36;
    constexpr int BS = 136;
    __shared__ uint32_t As[BM * AS];
    __shared__ uint32_t Bs[BK * BS];

    const int tid  = threadIdx.x;
    const int wid  = tid >> 5;
    const int lane = tid & 31;
    const int wm = wid & 1;
    const int wn = wid >> 1;
    const int brow = blockIdx.y * BM;

    float acc[4][4][4];
#pragma unroll
    for (int mt = 0; mt < 4; mt++)
#pragma unroll
        for (int nt = 0; nt < 4; nt++)
#pragma unroll
            for (int r = 0; r < 4; r++) acc[mt][nt][r] = 0.f;

#pragma unroll 1
    for (int pass = 0; pass < 2; pass++) {
        const float* A = pass ? A2 : A1;
        const float* B = pass ? B2 : B1;
        const int K   = pass ? K2 : K1;
#pragma unroll 1
        for (int k0 = 0; k0 < K; k0 += BK) {
#pragma unroll
            for (int p = 0; p < 4; p++) {
                const int idx = tid + p * 256;
                const int row = idx >> 3;
                const int c4  = (idx & 7) << 2;
                const int rg  = min(brow + row, Mclamp - 1);
                float4 v = *(const float4*)&A[(size_t)rg * K + k0 + c4];
                uint32_t* d = &As[row * AS + c4];
                d[0] = f2tf32(v.x); d[1] = f2tf32(v.y);
                d[2] = f2tf32(v.z); d[3] = f2tf32(v.w);
            }
#pragma unroll
            for (int p = 0; p < 4; p++) {
                const int idx = tid + p * 256;
                const int row = idx >> 5;
                const int c4  = (idx & 31) << 2;
                float4 v = *(const float4*)&B[(size_t)(k0 + row) * ldb + bofs + c4];
                uint32_t* d = &Bs[row * BS + c4];
                d[0] = f2tf32(v.x); d[1] = f2tf32(v.y);
                d[2] = f2tf32(v.z); d[3] = f2tf32(v.w);
            }
            __syncthreads();

#pragma unroll
            for (int ks = 0; ks < 4; ks++) {
                const int kk = ks * 8;
                uint32_t af[4][4];
#pragma unroll
                for (int mt = 0; mt < 4; mt++) {
                    const int r = wm * 64 + mt * 16 + (lane >> 2);
                    const int c = kk + (lane & 3);
                    af[mt][0] = As[r * AS + c];
                    af[mt][1] = As[(r + 8) * AS + c];
                    af[mt][2] = As[r * AS + c + 4];
                    af[mt][3] = As[(r + 8) * AS + c + 4];
                }
                uint32_t bf[4][2];
#pragma unroll
                for (int nt = 0; nt < 4; nt++) {
                    const int n = wn * 32 + nt * 8 + (lane >> 2);
                    const int k = kk + (lane & 3);
                    bf[nt][0] = Bs[k * BS + n];
                    bf[nt][1] = Bs[(k + 4) * BS + n];
                }
#pragma unroll
                for (int mt = 0; mt < 4; mt++)
#pragma unroll
                    for (int nt = 0; nt < 4; nt++)
                        mma_tf32(acc[mt][nt], af[mt][0], af[mt][1], af[mt][2],
                                 af[mt][3], bf[nt][0], bf[nt][1]);
            }
            __syncthreads();
        }
    }

    const int bcolC = blockIdx.x * 128;
#pragma unroll
    for (int nt = 0; nt < 4; nt++) {
        const int col = bcolC + wn * 32 + nt * 8 + ((lane & 3) << 1);
        float bx = 0.f, by = 0.f;
        if (bias) { bx = bias[col]; by = bias[col + 1]; }
#pragma unroll
        for (int mt = 0; mt < 4; mt++) {
            const int row0 = brow + wm * 64 + mt * 16 + (lane >> 2);
            float2 v0, v1;
            v0.x = acc[mt][nt][0] + bx;  v0.y = acc[mt][nt][1] + by;
            v1.x = acc[mt][nt][2] + bx;  v1.y = acc[mt][nt][3] + by;
            if (RELU) {
                v0.x = fmaxf(v0.x, 0.f); v0.y = fmaxf(v0.y, 0.f);
                v1.x = fmaxf(v1.x, 0.f); v1.y = fmaxf(v1.y, 0.f);
            }
            if (row0 < Mstore)
                *(float2*)&C[(size_t)row0 * ldc + col] = v0;
            if (row0 + 8 < Mstore)
                *(float2*)&C[(size_t)(row0 + 8) * ldc + col] = v1;
        }
    }
}

__global__ void __launch_bounds__(256)
k_gemm1(const float* __restrict__ x,
        const float* __restrict__ B1, const float* __restrict__ B2,
        const float* __restrict__ bias) {
    const int bofs = blockIdx.x * 128;
    tgemm<true>(g_mean1, 128, B1, x, 128, B2, 256, bofs, bias,
                g_h, 256, N_NODES, N_NODES);
}

__global__ void __launch_bounds__(256)
k_gemm2(const float* __restrict__ w2l, const float* __restrict__ w2r) {
    const float* B = blockIdx.x ? w2r : w2l;
    tgemm<false>(g_h, 256, B, nullptr, 0, nullptr, 128, 0, nullptr,
                 g_pr, 256, N_NODES, N_NODES);
}

// ---------------- launch -------------------------------------------------------
extern "C" void kernel_launch(void* const* d_in, const int* in_sizes, int n_in,
                              void* d_out, int out_size) {
    const float* x    = (const float*)d_in[0];
    const int*   ei32 = (const int*)d_in[1];
    const float* w1_l = (const float*)d_in[2];
    const float* b1_l = (const float*)d_in[3];
    const float* w1_r = (const float*)d_in[4];
    const float* w2_l = (const float*)d_in[5];
    const float* b2_l = (const float*)d_in[6];
    const float* w2_r = (const float*)d_in[7];
    float* out = (float*)d_out;

    k_detect<<<1, 1>>>(ei32);
    k_zero_cnt<<<(N_NODES + 255) / 256, 256>>>();
    k_conv_hist<<<(N_EDGES + 255) / 256, 256>>>(ei32);
    k_scan_blk<<<SCAN_NBLK, SCAN_BLK>>>();
    k_scan_top<<<1, 128>>>();
    k_scan_add<<<SCAN_NBLK, SCAN_BLK>>>();
    k_scatter<<<(N_EDGES + 255) / 256, 256>>>();

    k_agg1<<<(N_NODES + 7) / 8, 256>>>(x);
    {
        dim3 grid(2, NPAD / 128);
        k_gemm1<<<grid, 256>>>(x, w1_l, w1_r, b1_l);
    }
    {
        dim3 grid(2, NPAD / 128);
        k_gemm2<<<grid, 256>>>(w2_l, w2_r);
    }
    k_agg2b<<<(N_NODES + 7) / 8, 256>>>(b2_l, out);
}